// round 1
// baseline (speedup 1.0000x reference)
#include <cuda_runtime.h>

#define BB 4
#define NN 1024
#define CC 1024
#define HH 16
#define HDIM 64

// ---------------- scratch (static __device__, allocation-free) ----------------
__device__ float g_q[(size_t)BB*HH*NN*HDIM];
__device__ float g_k[(size_t)BB*HH*NN*HDIM];
__device__ float g_v[(size_t)BB*HH*NN*HDIM];
__device__ float g_mid[(size_t)BB*NN*CC];
__device__ float g_inv[(size_t)BB*HH*NN];

// ---------------- K1: qkv = x @ qkv_w^T + qkv_b, scatter to q/k/v ----------------
// M=4096 (b,n), N=3072 (which,h,d), K=1024. 128x128x16 tiles, 256 threads, 8x8 micro.
__global__ __launch_bounds__(256) void qkv_kernel(
    const float* __restrict__ x, const float* __restrict__ w, const float* __restrict__ bias) {
  __shared__ float As[16][128];
  __shared__ float Bs[16][128];
  const int rb = blockIdx.y * 128;
  const int ob = blockIdx.x * 128;
  const int tid = threadIdx.x;
  const int ty = tid >> 4, tx = tid & 15;
  const int row0 = ty * 8, col0 = tx * 8;
  float acc[8][8];
#pragma unroll
  for (int i = 0; i < 8; i++)
#pragma unroll
    for (int j = 0; j < 8; j++) acc[i][j] = 0.f;

  for (int k0 = 0; k0 < CC; k0 += 16) {
#pragma unroll
    for (int i = 0; i < 2; i++) {
      int f = tid + 256 * i;
      int r = f >> 2, kq = (f & 3) << 2;
      float4 a4 = *(const float4*)(x + (size_t)(rb + r) * CC + k0 + kq);
      As[kq + 0][r] = a4.x; As[kq + 1][r] = a4.y; As[kq + 2][r] = a4.z; As[kq + 3][r] = a4.w;
      float4 b4 = *(const float4*)(w + (size_t)(ob + r) * CC + k0 + kq);
      Bs[kq + 0][r] = b4.x; Bs[kq + 1][r] = b4.y; Bs[kq + 2][r] = b4.z; Bs[kq + 3][r] = b4.w;
    }
    __syncthreads();
#pragma unroll
    for (int kk = 0; kk < 16; kk++) {
      float a[8], b[8];
      *(float4*)&a[0] = *(const float4*)&As[kk][row0];
      *(float4*)&a[4] = *(const float4*)&As[kk][row0 + 4];
      *(float4*)&b[0] = *(const float4*)&Bs[kk][col0];
      *(float4*)&b[4] = *(const float4*)&Bs[kk][col0 + 4];
#pragma unroll
      for (int i = 0; i < 8; i++)
#pragma unroll
        for (int j = 0; j < 8; j++) acc[i][j] += a[i] * b[j];
    }
    __syncthreads();
  }

  // epilogue: decompose o -> (which, h, d). 8 consecutive o stay in one (which,h) block.
  const int o0 = ob + col0;
  const int which = o0 >> 10;
  const int h = (o0 >> 6) & 15;
  const int d0 = o0 & 63;
  float bias8[8];
  *(float4*)&bias8[0] = *(const float4*)(bias + o0);
  *(float4*)&bias8[4] = *(const float4*)(bias + o0 + 4);
  float* dst = (which == 0) ? g_q : (which == 1) ? g_k : g_v;
  const float sc = (which == 0) ? 0.125f : 1.0f;  // HD^-0.5 = 1/8
#pragma unroll
  for (int i = 0; i < 8; i++) {
    int r = rb + row0 + i;
    int b = r >> 10, n = r & 1023;
    size_t base = ((((size_t)b * HH + h) * NN + n) * HDIM) + d0;
    float v[8];
#pragma unroll
    for (int j = 0; j < 8; j++) v[j] = (acc[i][j] + bias8[j]) * sc;
    *(float4*)(dst + base) = make_float4(v[0], v[1], v[2], v[3]);
    *(float4*)(dst + base + 4) = make_float4(v[4], v[5], v[6], v[7]);
  }
}

// ---------------- K2: t[b,g,n,m] = sum_h wl[g,h] (q_h . k_h) + bl[g] ----------------
// CTA = (m-tile 32, n-tile 32, b). 256 threads, each owns 2n x 2m x 16g accumulators.
__global__ __launch_bounds__(256) void logits_kernel(
    const float* __restrict__ wl, const float* __restrict__ bl, float* __restrict__ attn) {
  __shared__ float Qs[32][65];
  __shared__ float Ks[32][65];
  __shared__ float wls[256];
  __shared__ float bls[16];
  const int b = blockIdx.z;
  const int nb = blockIdx.y * 32;
  const int mb = blockIdx.x * 32;
  const int tid = threadIdx.x;
  wls[tid] = wl[tid];
  if (tid < 16) bls[tid] = bl[tid];
  const int nl = (tid >> 4) * 2;
  const int ml = (tid & 15) * 2;
  float t00[16], t01[16], t10[16], t11[16];
#pragma unroll
  for (int g = 0; g < 16; g++) { t00[g] = 0.f; t01[g] = 0.f; t10[g] = 0.f; t11[g] = 0.f; }

  for (int h = 0; h < 16; h++) {
    __syncthreads();
#pragma unroll
    for (int i = 0; i < 2; i++) {
      int f = tid + 256 * i;
      int r = f >> 4, dq = (f & 15) << 2;
      const float* qp = g_q + ((((size_t)b * 16 + h) * 1024) + nb + r) * 64 + dq;
      float4 q4 = *(const float4*)qp;
      Qs[r][dq] = q4.x; Qs[r][dq + 1] = q4.y; Qs[r][dq + 2] = q4.z; Qs[r][dq + 3] = q4.w;
      const float* kp = g_k + ((((size_t)b * 16 + h) * 1024) + mb + r) * 64 + dq;
      float4 k4 = *(const float4*)kp;
      Ks[r][dq] = k4.x; Ks[r][dq + 1] = k4.y; Ks[r][dq + 2] = k4.z; Ks[r][dq + 3] = k4.w;
    }
    __syncthreads();
    float s00 = 0.f, s01 = 0.f, s10 = 0.f, s11 = 0.f;
#pragma unroll 16
    for (int d = 0; d < 64; d++) {
      float q0 = Qs[nl][d], q1 = Qs[nl + 1][d];
      float k0 = Ks[ml][d], k1 = Ks[ml + 1][d];
      s00 += q0 * k0; s01 += q0 * k1; s10 += q1 * k0; s11 += q1 * k1;
    }
#pragma unroll
    for (int g = 0; g < 16; g++) {
      float wv = wls[g * 16 + h];
      t00[g] += wv * s00; t01[g] += wv * s01;
      t10[g] += wv * s10; t11[g] += wv * s11;
    }
  }
#pragma unroll
  for (int g = 0; g < 16; g++) {
    float blg = bls[g];
    size_t rowbase = ((size_t)b * 16 + g) * 1024;
    float* p0 = attn + (rowbase + nb + nl) * 1024 + mb + ml;
    *(float2*)p0 = make_float2(t00[g] + blg, t01[g] + blg);
    float* p1 = attn + (rowbase + nb + nl + 1) * 1024 + mb + ml;
    *(float2*)p1 = make_float2(t10[g] + blg, t11[g] + blg);
  }
}

// ---------------- K3a: in-place row softmax numerator; 1/sum to g_inv ----------------
// One warp per (b,g,n) row of 1024. Values in registers.
__global__ __launch_bounds__(256) void softmax_kernel(float* __restrict__ attn) {
  const int warp = threadIdx.x >> 5, lane = threadIdx.x & 31;
  const int row = blockIdx.x * 8 + warp;  // 0..65535
  float* p = attn + (size_t)row * 1024;
  float vals[32];
#pragma unroll
  for (int j = 0; j < 8; j++) {
    float4 v = *(const float4*)(p + lane * 4 + 128 * j);
    vals[j * 4 + 0] = v.x; vals[j * 4 + 1] = v.y; vals[j * 4 + 2] = v.z; vals[j * 4 + 3] = v.w;
  }
  float mx = -1e30f;
#pragma unroll
  for (int i = 0; i < 32; i++) mx = fmaxf(mx, vals[i]);
#pragma unroll
  for (int o = 16; o; o >>= 1) mx = fmaxf(mx, __shfl_xor_sync(0xffffffffu, mx, o));
  float sum = 0.f;
#pragma unroll
  for (int i = 0; i < 32; i++) { vals[i] = __expf(vals[i] - mx); sum += vals[i]; }
#pragma unroll
  for (int o = 16; o; o >>= 1) sum += __shfl_xor_sync(0xffffffffu, sum, o);
  float inv = 1.0f / sum;
#pragma unroll
  for (int j = 0; j < 8; j++) {
    *(float4*)(p + lane * 4 + 128 * j) =
        make_float4(vals[j * 4 + 0], vals[j * 4 + 1], vals[j * 4 + 2], vals[j * 4 + 3]);
  }
  if (lane == 0) g_inv[row] = inv;
}

// ---------------- K3b: attn[b,g,n,m] = sum_h ww[g,h]*p[h,n,m] + bw[g] (in place) ----------------
// CTA per (b,n). Each thread owns distinct m columns -> in-place safe.
__global__ __launch_bounds__(256) void mix2_kernel(
    const float* __restrict__ ww, const float* __restrict__ bw, float* __restrict__ attn) {
  __shared__ float wws[256];
  __shared__ float bws[16];
  __shared__ float invs[16];
  const int n = blockIdx.x;
  const int b = blockIdx.y;
  const int tid = threadIdx.x;
  wws[tid] = ww[tid];
  if (tid < 16) {
    bws[tid] = bw[tid];
    invs[tid] = g_inv[((size_t)b * 16 + tid) * 1024 + n];
  }
  __syncthreads();
#pragma unroll
  for (int mi = 0; mi < 4; mi++) {
    int m = tid + mi * 256;
    float pv[16];
#pragma unroll
    for (int h = 0; h < 16; h++)
      pv[h] = attn[((((size_t)b * 16 + h) * 1024) + n) * 1024 + m] * invs[h];
#pragma unroll
    for (int g = 0; g < 16; g++) {
      float a = bws[g];
#pragma unroll
      for (int h = 0; h < 16; h++) a += wws[g * 16 + h] * pv[h];
      attn[((((size_t)b * 16 + g) * 1024) + n) * 1024 + m] = a;
    }
  }
}

// ---------------- K4: mid[b,n,g*64+d] = sum_m attn[b,g,n,m] * v[b,g,m,d] ----------------
// Batched over (b,g). 64n x 64d tiles, k-tile 32, 256 threads, 4x4 micro.
__global__ __launch_bounds__(256) void av_kernel(const float* __restrict__ attn) {
  __shared__ float As[32][68];
  __shared__ float Vs[32][68];
  const int bg = blockIdx.y;
  const int b = bg >> 4, g = bg & 15;
  const int nb = blockIdx.x * 64;
  const int tid = threadIdx.x;
  const int ty = tid >> 4, tx = tid & 15;
  const int n0 = ty * 4, d0 = tx * 4;
  const size_t arow = ((size_t)b * 16 + g) * 1024;
  float acc[4][4];
#pragma unroll
  for (int i = 0; i < 4; i++)
#pragma unroll
    for (int j = 0; j < 4; j++) acc[i][j] = 0.f;

  for (int k0 = 0; k0 < 1024; k0 += 32) {
#pragma unroll
    for (int i = 0; i < 2; i++) {
      int f = tid + 256 * i;  // 0..511
      int r = f >> 3, mq = (f & 7) << 2;
      float4 a4 = *(const float4*)(attn + (arow + nb + r) * 1024 + k0 + mq);
      As[mq + 0][r] = a4.x; As[mq + 1][r] = a4.y; As[mq + 2][r] = a4.z; As[mq + 3][r] = a4.w;
      int m = f >> 4, dq = (f & 15) << 2;
      float4 v4 = *(const float4*)(g_v + (arow + k0 + m) * 64 + dq);
      *(float4*)&Vs[m][dq] = v4;
    }
    __syncthreads();
#pragma unroll
    for (int kk = 0; kk < 32; kk++) {
      float4 av = *(const float4*)&As[kk][n0];
      float4 vv = *(const float4*)&Vs[kk][d0];
      float a[4] = {av.x, av.y, av.z, av.w};
      float v[4] = {vv.x, vv.y, vv.z, vv.w};
#pragma unroll
      for (int i = 0; i < 4; i++)
#pragma unroll
        for (int j = 0; j < 4; j++) acc[i][j] += a[i] * v[j];
    }
    __syncthreads();
  }
#pragma unroll
  for (int i = 0; i < 4; i++) {
    int n = nb + n0 + i;
    float* dst = g_mid + ((size_t)b * 1024 + n) * 1024 + g * 64 + d0;
    *(float4*)dst = make_float4(acc[i][0], acc[i][1], acc[i][2], acc[i][3]);
  }
}

// ---------------- K5: out = mid @ proj_w^T + proj_b ----------------
__global__ __launch_bounds__(256) void proj_kernel(
    const float* __restrict__ w, const float* __restrict__ bias, float* __restrict__ out) {
  __shared__ float As[16][128];
  __shared__ float Bs[16][128];
  const int rb = blockIdx.y * 128;
  const int ob = blockIdx.x * 128;
  const int tid = threadIdx.x;
  const int ty = tid >> 4, tx = tid & 15;
  const int row0 = ty * 8, col0 = tx * 8;
  float acc[8][8];
#pragma unroll
  for (int i = 0; i < 8; i++)
#pragma unroll
    for (int j = 0; j < 8; j++) acc[i][j] = 0.f;

  for (int k0 = 0; k0 < CC; k0 += 16) {
#pragma unroll
    for (int i = 0; i < 2; i++) {
      int f = tid + 256 * i;
      int r = f >> 2, kq = (f & 3) << 2;
      float4 a4 = *(const float4*)(g_mid + (size_t)(rb + r) * CC + k0 + kq);
      As[kq + 0][r] = a4.x; As[kq + 1][r] = a4.y; As[kq + 2][r] = a4.z; As[kq + 3][r] = a4.w;
      float4 b4 = *(const float4*)(w + (size_t)(ob + r) * CC + k0 + kq);
      Bs[kq + 0][r] = b4.x; Bs[kq + 1][r] = b4.y; Bs[kq + 2][r] = b4.z; Bs[kq + 3][r] = b4.w;
    }
    __syncthreads();
#pragma unroll
    for (int kk = 0; kk < 16; kk++) {
      float a[8], b[8];
      *(float4*)&a[0] = *(const float4*)&As[kk][row0];
      *(float4*)&a[4] = *(const float4*)&As[kk][row0 + 4];
      *(float4*)&b[0] = *(const float4*)&Bs[kk][col0];
      *(float4*)&b[4] = *(const float4*)&Bs[kk][col0 + 4];
#pragma unroll
      for (int i = 0; i < 8; i++)
#pragma unroll
        for (int j = 0; j < 8; j++) acc[i][j] += a[i] * b[j];
    }
    __syncthreads();
  }
  const int o0 = ob + col0;
  float bias8[8];
  *(float4*)&bias8[0] = *(const float4*)(bias + o0);
  *(float4*)&bias8[4] = *(const float4*)(bias + o0 + 4);
#pragma unroll
  for (int i = 0; i < 8; i++) {
    int r = rb + row0 + i;
    float v[8];
#pragma unroll
    for (int j = 0; j < 8; j++) v[j] = acc[i][j] + bias8[j];
    *(float4*)(out + (size_t)r * CC + o0) = make_float4(v[0], v[1], v[2], v[3]);
    *(float4*)(out + (size_t)r * CC + o0 + 4) = make_float4(v[4], v[5], v[6], v[7]);
  }
}

// ---------------- launch ----------------
extern "C" void kernel_launch(void* const* d_in, const int* in_sizes, int n_in,
                              void* d_out, int out_size) {
  const float* x      = (const float*)d_in[0];
  const float* qkv_w  = (const float*)d_in[1];
  const float* qkv_b  = (const float*)d_in[2];
  const float* proj_w = (const float*)d_in[3];
  const float* proj_b = (const float*)d_in[4];
  const float* wl     = (const float*)d_in[5];
  const float* bl     = (const float*)d_in[6];
  const float* ww     = (const float*)d_in[7];
  const float* bw     = (const float*)d_in[8];
  float* out = (float*)d_out;
  float* attn = out + (size_t)BB * NN * CC;  // output tuple: out first, then attn

  qkv_kernel<<<dim3(24, 32), 256>>>(x, qkv_w, qkv_b);
  logits_kernel<<<dim3(32, 32, 4), 256>>>(wl, bl, attn);
  softmax_kernel<<<8192, 256>>>(attn);
  mix2_kernel<<<dim3(1024, 4), 256>>>(ww, bw, attn);
  av_kernel<<<dim3(16, 64), 256>>>(attn);
  proj_kernel<<<dim3(8, 32), 256>>>(proj_w, proj_b, out);
}